// round 4
// baseline (speedup 1.0000x reference)
#include <cuda_runtime.h>
#include <cuda_bf16.h>
#include <cstdint>
#include <cstddef>

// Problem dims (fixed by the dataset)
#define SEQ_L 2048
#define BATCH 8
#define DIM   2048
#define M_ROWS (SEQ_L * BATCH)   // 16384
#define K_DIM  DIM               // 2048
#define N_DIM  DIM               // 2048

// GEMM tiling
#define MT 256
#define NT 128
#define KT 32                    // 32 bf16 = 64B of K per chunk
#define NCHUNK (K_DIM / KT)      // 64
#define ROWB 80                  // padded smem row stride (64B data + 16B pad)

// SMEM stage layout (byte offsets within one stage)
#define OFF_AHI 0
#define OFF_ALO (MT * ROWB)                 // 20480
#define OFF_BHI (2 * MT * ROWB)             // 40960
#define OFF_BLO (2 * MT * ROWB + NT * ROWB) // 51200
#define STAGE   (2 * MT * ROWB + 2 * NT * ROWB)  // 61440
#define SMEM_TOTAL (2 * STAGE)                   // 122880

// Scratch (device globals — allocation-free rule)
__device__ __nv_bfloat16 g_xhi[(size_t)M_ROWS * K_DIM];
__device__ __nv_bfloat16 g_xlo[(size_t)M_ROWS * K_DIM];
__device__ __nv_bfloat16 g_whi[(size_t)N_DIM * K_DIM];
__device__ __nv_bfloat16 g_wlo[(size_t)N_DIM * K_DIM];

// ---------------- PTX helpers (sm_80-era only: safe at compute_103) ----------------
__device__ __forceinline__ uint32_t smem_u32(const void* p) {
    uint32_t a;
    asm("{ .reg .u64 t; cvta.to.shared.u64 t, %1; cvt.u32.u64 %0, t; }"
        : "=r"(a) : "l"(p));
    return a;
}

__device__ __forceinline__ void cp_async16(uint32_t saddr, const void* gaddr) {
    asm volatile("cp.async.cg.shared.global [%0], [%1], 16;"
                 :: "r"(saddr), "l"(gaddr) : "memory");
}

__device__ __forceinline__ void ldsm_x4(uint32_t (&r)[4], uint32_t addr) {
    asm volatile("ldmatrix.sync.aligned.m8n8.x4.shared.b16 {%0,%1,%2,%3}, [%4];"
                 : "=r"(r[0]), "=r"(r[1]), "=r"(r[2]), "=r"(r[3]) : "r"(addr));
}

// B fragment for mma.row.col from [N,K]-row-major smem: NON-trans x2.
// Lane l receives storage(row = l/4 = n, cols (l%4)*2 = k pair) — exactly the
// required b0 = {B[k0,n], B[k0+1,n]} layout. (.trans here was the R3 bug.)
__device__ __forceinline__ void ldsm_x2(uint32_t (&r)[2], uint32_t addr) {
    asm volatile("ldmatrix.sync.aligned.m8n8.x2.shared.b16 {%0,%1}, [%2];"
                 : "=r"(r[0]), "=r"(r[1]) : "r"(addr));
}

__device__ __forceinline__ void mma_bf16(float (&d)[4], const uint32_t (&a)[4],
                                         const uint32_t (&b)[2]) {
    asm volatile(
        "mma.sync.aligned.m16n8k16.row.col.f32.bf16.bf16.f32 "
        "{%0,%1,%2,%3}, {%4,%5,%6,%7}, {%8,%9}, {%0,%1,%2,%3};"
        : "+f"(d[0]), "+f"(d[1]), "+f"(d[2]), "+f"(d[3])
        : "r"(a[0]), "r"(a[1]), "r"(a[2]), "r"(a[3]), "r"(b[0]), "r"(b[1]));
}

// ---------------- Kernel 1: EMA scan + bf16 hi/lo split ----------------
// conv[t] = f*conv[t-1] + x[t];  x_mix[t] = xml*f^{t+1} + (1-f)*conv[t]
__global__ void __launch_bounds__(256) scan_kernel(const float* __restrict__ x,
                                                   const float* __restrict__ xml,
                                                   const float* __restrict__ fparam) {
    const int idx = blockIdx.x * blockDim.x + threadIdx.x;   // 0..16383 = b*D + d
    const int d = idx & (DIM - 1);
    const float f = 1.0f / (1.0f + expf(-fparam[d]));
    const float omf = 1.0f - f;
    float c = 0.0f;
    float m = xml[idx];
    const float* px = x + idx;
    __nv_bfloat16* ph = g_xhi + idx;
    __nv_bfloat16* pl = g_xlo + idx;

    const int STRIDE = BATCH * DIM;   // 16384
    constexpr int U = 16;
    for (int t = 0; t < SEQ_L; t += U) {
        float xv[U];
#pragma unroll
        for (int u = 0; u < U; u++) xv[u] = px[(t + u) * STRIDE];
#pragma unroll
        for (int u = 0; u < U; u++) {
            c = fmaf(f, c, xv[u]);
            m *= f;
            float xm = fmaf(omf, c, m);
            __nv_bfloat16 hi = __float2bfloat16(xm);
            float lo = xm - __bfloat162float(hi);
            ph[(t + u) * STRIDE] = hi;
            pl[(t + u) * STRIDE] = __float2bfloat16(lo);
        }
    }
}

// ---------------- Kernel 2: W hi/lo split ----------------
__global__ void __launch_bounds__(256) wsplit_kernel(const float* __restrict__ W) {
    const int i = blockIdx.x * blockDim.x + threadIdx.x;
    float w = W[i];
    __nv_bfloat16 hi = __float2bfloat16(w);
    g_whi[i] = hi;
    g_wlo[i] = __float2bfloat16(w - __bfloat162float(hi));
}

// ---------------- Kernel 3: compensated bf16 GEMM via mma.sync ----------------
// out[m,n] = sum_k x_mix[m,k] * W[n,k]
__device__ __forceinline__ void load_chunk(uint32_t sb, int tid, int m0, int n0, int ck) {
    const uint32_t tb = sb + (uint32_t)(ck & 1) * STAGE;
    const int koff = ck * KT;   // element offset in K

    // A: 256 rows; thread t copies row t (4 x 16B) of both hi and lo
    const size_t ga = (size_t)(m0 + tid) * K_DIM + koff;
    const uint32_t sa = tb + (uint32_t)tid * ROWB;
#pragma unroll
    for (int s = 0; s < 4; s++) {
        cp_async16(sa + OFF_AHI + s * 16, g_xhi + ga + s * 8);
        cp_async16(sa + OFF_ALO + s * 16, g_xlo + ga + s * 8);
    }
    // B: 128 rows; threads 0-127 copy hi, 128-255 copy lo
    const int brow = tid & 127;
    const __nv_bfloat16* gb = (tid < 128) ? g_whi : g_wlo;
    const uint32_t ob = (tid < 128) ? OFF_BHI : OFF_BLO;
    const size_t gB = (size_t)(n0 + brow) * K_DIM + koff;
    const uint32_t sB = tb + ob + (uint32_t)brow * ROWB;
#pragma unroll
    for (int s = 0; s < 4; s++) cp_async16(sB + s * 16, gb + gB + s * 8);

    asm volatile("cp.async.commit_group;" ::: "memory");
}

__global__ void __launch_bounds__(256, 1) gemm_kernel(float* __restrict__ out) {
    extern __shared__ char smem[];
    const uint32_t sb = smem_u32(smem);
    const int tid = threadIdx.x;
    const int lid = tid & 31;
    const int wid = tid >> 5;
    const int wm = wid & 3;     // 4 warps along M (64 rows each)
    const int wn = wid >> 2;    // 2 warps along N (64 cols each)
    const int m0 = blockIdx.x * MT;
    const int n0 = blockIdx.y * NT;

    float acc[4][8][4];
#pragma unroll
    for (int a = 0; a < 4; a++)
#pragma unroll
        for (int b = 0; b < 8; b++)
#pragma unroll
            for (int c = 0; c < 4; c++) acc[a][b][c] = 0.0f;

    // Per-lane ldmatrix relative byte offsets (within a stage).
    // A (x4): lanes 0-7 rows 0-7 @k0, 8-15 rows 8-15 @k0, 16-23 rows 0-7 @k8,
    //         24-31 rows 8-15 @k8  -> regs map to a0..a3 of m16n8k16 A.
    // B (x2, non-trans): lanes 0-7 rows n0..7 @k0 (16B), lanes 8-15 same rows @k8.
    const int lsel = lid & 15;
    uint32_t relA[4], relB[8];
#pragma unroll
    for (int mt = 0; mt < 4; mt++)
        relA[mt] = (uint32_t)((wm * 64 + mt * 16 + (lid & 15)) * ROWB + (lid >> 4) * 16);
#pragma unroll
    for (int nt = 0; nt < 8; nt++)
        relB[nt] = (uint32_t)((wn * 64 + nt * 8 + (lsel & 7)) * ROWB + ((lsel >> 3) & 1) * 16);

    load_chunk(sb, tid, m0, n0, 0);

    for (int i = 0; i < NCHUNK; i++) {
        if (i + 1 < NCHUNK) {
            load_chunk(sb, tid, m0, n0, i + 1);
            asm volatile("cp.async.wait_group 1;" ::: "memory");
        } else {
            asm volatile("cp.async.wait_group 0;" ::: "memory");
        }
        __syncthreads();

        const uint32_t base = sb + (uint32_t)(i & 1) * STAGE;
#pragma unroll
        for (int ks = 0; ks < 2; ks++) {
            const uint32_t ko = (uint32_t)ks * 32;
            uint32_t ahi[4][4], bfr[8][2];
#pragma unroll
            for (int mt = 0; mt < 4; mt++) ldsm_x4(ahi[mt], base + OFF_AHI + relA[mt] + ko);
#pragma unroll
            for (int nt = 0; nt < 8; nt++) ldsm_x2(bfr[nt], base + OFF_BHI + relB[nt] + ko);
            // pass 1: hi * hi
#pragma unroll
            for (int mt = 0; mt < 4; mt++)
#pragma unroll
                for (int nt = 0; nt < 8; nt++) mma_bf16(acc[mt][nt], ahi[mt], bfr[nt]);
            // pass 2: lo * hi (reuse B-hi fragments)
            {
                uint32_t alo[4][4];
#pragma unroll
                for (int mt = 0; mt < 4; mt++) ldsm_x4(alo[mt], base + OFF_ALO + relA[mt] + ko);
#pragma unroll
                for (int mt = 0; mt < 4; mt++)
#pragma unroll
                    for (int nt = 0; nt < 8; nt++) mma_bf16(acc[mt][nt], alo[mt], bfr[nt]);
            }
            // pass 3: hi * lo (reuse A-hi fragments)
#pragma unroll
            for (int nt = 0; nt < 8; nt++) ldsm_x2(bfr[nt], base + OFF_BLO + relB[nt] + ko);
#pragma unroll
            for (int mt = 0; mt < 4; mt++)
#pragma unroll
                for (int nt = 0; nt < 8; nt++) mma_bf16(acc[mt][nt], ahi[mt], bfr[nt]);
        }
        __syncthreads();
    }

    // Epilogue: direct stores (m16n8 fragment: lane l -> row l/4 (+8), cols (l%4)*2, +1)
    const int l4 = lid >> 2;
    const int l2 = (lid & 3) * 2;
#pragma unroll
    for (int mt = 0; mt < 4; mt++) {
        const size_t r = (size_t)(m0 + wm * 64 + mt * 16 + l4);
        float* p0 = out + r * N_DIM + (n0 + wn * 64 + l2);
        float* p1 = p0 + (size_t)8 * N_DIM;
#pragma unroll
        for (int nt = 0; nt < 8; nt++) {
            *reinterpret_cast<float2*>(p0 + nt * 8) =
                make_float2(acc[mt][nt][0], acc[mt][nt][1]);
            *reinterpret_cast<float2*>(p1 + nt * 8) =
                make_float2(acc[mt][nt][2], acc[mt][nt][3]);
        }
    }
}

// ---------------- launch ----------------
extern "C" void kernel_launch(void* const* d_in, const int* in_sizes, int n_in,
                              void* d_out, int out_size) {
    const float *x = nullptr, *xml = nullptr, *fp = nullptr, *W = nullptr;
    for (int i = 0; i < n_in; i++) {
        int s = in_sizes[i];
        if (s == SEQ_L * BATCH * DIM)      x   = (const float*)d_in[i];
        else if (s == BATCH * DIM)         xml = (const float*)d_in[i];
        else if (s == DIM)                 fp  = (const float*)d_in[i];
        else if (s == DIM * DIM)           W   = (const float*)d_in[i];
    }

    cudaFuncSetAttribute(gemm_kernel, cudaFuncAttributeMaxDynamicSharedMemorySize, SMEM_TOTAL);

    scan_kernel<<<(BATCH * DIM) / 256, 256>>>(x, xml, fp);
    wsplit_kernel<<<(DIM * DIM) / 256, 256>>>(W);
    gemm_kernel<<<dim3(M_ROWS / MT, N_DIM / NT), 256, SMEM_TOTAL>>>((float*)d_out);
}